// round 16
// baseline (speedup 1.0000x reference)
#include <cuda_runtime.h>
#include <cuda_fp16.h>
#include <cstdint>

// ============================================================================
// Problem constants
// ============================================================================
#define T_TOKENS 4096
#define IN_F     4096
#define OUT_F    4096
#define NNZ      512

// GEMM tiling: CTA 128x128, warp tile 64x32 (8 warps, 2x4), 2 CTAs/SM.
static constexpr int BM = 128;
static constexpr int BN = 128;
static constexpr int BK = 64;                 // fp16 -> 128B rows (SW128 atom)
static constexpr int KITERS = IN_F / BK;      // 64
static constexpr int STAGES = 3;
static constexpr int STAGE_BYTES = (BM * BK + BN * BK) * 2;  // 32768
static constexpr int MBAR_BASE  = STAGES * STAGE_BYTES;      // 98304
static constexpr int SMEM_TOTAL = MBAR_BASE + 64;            // 98368

// prep: conv blocks do 8 float4 per thread (MLP=8)
static constexpr int CONV_BLOCKS = (T_TOKENS * IN_F / 4) / (256 * 8);  // 2048

// ============================================================================
// Scratch (device globals — no allocation allowed)
// ============================================================================
__device__ __align__(16) __half g_xh[(size_t)T_TOKENS * IN_F];  // 32 MB fp16 x
__device__ __align__(16) __half g_wh[(size_t)OUT_F * IN_F];     // 32 MB fp16 dense W

// ============================================================================
// Helpers
// ============================================================================
__device__ __forceinline__ uint32_t smem_u32(const void* p) {
    uint32_t a;
    asm("{ .reg .u64 t; cvta.to.shared.u64 t, %1; cvt.u32.u64 %0, t; }"
        : "=r"(a) : "l"(p));
    return a;
}
#define SW128(o) ((o) ^ (((o) >> 3) & 0x70))

__device__ __forceinline__ void cp_async16(uint32_t dst, const void* src) {
    asm volatile("cp.async.cg.shared.global [%0], [%1], 16;" :: "r"(dst), "l"(src));
}
__device__ __forceinline__ void cp_async_mbar_arrive(uint32_t mbar) {
    asm volatile("cp.async.mbarrier.arrive.noinc.shared.b64 [%0];"
                 :: "r"(mbar) : "memory");
}
__device__ __forceinline__ void mbar_init(uint32_t mbar, uint32_t cnt) {
    asm volatile("mbarrier.init.shared.b64 [%0], %1;" :: "r"(mbar), "r"(cnt)
                 : "memory");
}
__device__ __forceinline__ void mbar_arrive(uint32_t mbar) {
    asm volatile("mbarrier.arrive.release.cta.shared::cta.b64 _, [%0];"
                 :: "r"(mbar) : "memory");
}
__device__ __forceinline__ void mbar_wait(uint32_t mbar, uint32_t parity) {
    uint32_t done;
    asm volatile("{ .reg .pred p;\n\t"
        "mbarrier.try_wait.parity.acquire.cta.shared::cta.b64 p, [%1], %2;\n\t"
        "selp.b32 %0, 1, 0, p; }"
        : "=r"(done) : "r"(mbar), "r"(parity) : "memory");
    if (!done) {
        asm volatile("{ .reg .pred P1;\n\t"
            "WAIT_LOOP_%=:\n\t"
            "mbarrier.try_wait.parity.acquire.cta.shared::cta.b64 P1, [%0], %1, 0x989680;\n\t"
            "@P1 bra.uni WAIT_DONE_%=;\n\t"
            "bra.uni WAIT_LOOP_%=;\n\t"
            "WAIT_DONE_%=: }"
            :: "r"(mbar), "r"(parity) : "memory");
    }
}
__device__ __forceinline__ void ldmatrix_x4(uint32_t* r, uint32_t addr) {
    asm volatile("ldmatrix.sync.aligned.m8n8.x4.shared.b16 {%0,%1,%2,%3}, [%4];"
                 : "=r"(r[0]), "=r"(r[1]), "=r"(r[2]), "=r"(r[3]) : "r"(addr));
}
__device__ __forceinline__ void mma16816(float* c, const uint32_t* a,
                                         uint32_t b0, uint32_t b1) {
    asm volatile(
        "mma.sync.aligned.m16n8k16.row.col.f32.f16.f16.f32 "
        "{%0,%1,%2,%3}, {%4,%5,%6,%7}, {%8,%9}, {%0,%1,%2,%3};"
        : "+f"(c[0]), "+f"(c[1]), "+f"(c[2]), "+f"(c[3])
        : "r"(a[0]), "r"(a[1]), "r"(a[2]), "r"(a[3]), "r"(b0), "r"(b1));
}
__device__ __forceinline__ float4 ldcs4(const float4* p) {
    float4 v;
    asm volatile("ld.global.cs.v4.f32 {%0,%1,%2,%3}, [%4];"
                 : "=f"(v.x), "=f"(v.y), "=f"(v.z), "=f"(v.w) : "l"(p));
    return v;
}
__device__ __forceinline__ int4 ldcs4i(const int4* p) {
    int4 v;
    asm volatile("ld.global.cs.v4.b32 {%0,%1,%2,%3}, [%4];"
                 : "=r"(v.x), "=r"(v.y), "=r"(v.z), "=r"(v.w) : "l"(p));
    return v;
}
__device__ __forceinline__ uint32_t h2_bits(__half2 h) {
    uint32_t u;
    memcpy(&u, &h, 4);
    return u;
}
// streaming 8B store (evict-first: keep g_xh/g_wh resident in L2)
__device__ __forceinline__ void stcs2(float* p, float2 v) {
    asm volatile("st.global.cs.v2.f32 [%0], {%1, %2};"
                 :: "l"(p), "f"(v.x), "f"(v.y) : "memory");
}

// ============================================================================
// Kernel 1 (fused prep):
//   blocks [0, CONV_BLOCKS): convert x fp32->fp16, 8 independent float4 per
//   thread (MLP=8), x read with .cs (read-once, keep L2 for g_xh/g_wh).
//   blocks [CONV_BLOCKS, +OUT_F): densify one W row each. Vectorized smem
//   zero-fill (float4) and packed 8B g_wh stores cut per-row latency.
// ============================================================================
__global__ void __launch_bounds__(256) k_prep(const float4* __restrict__ x,
                                              const float* __restrict__ w,
                                              const int* __restrict__ mask) {
    if (blockIdx.x < CONV_BLOCKS) {
        const size_t base = (size_t)blockIdx.x * (256 * 8) + threadIdx.x;
        float4 v[8];
        #pragma unroll
        for (int i = 0; i < 8; ++i) v[i] = ldcs4(&x[base + i * 256]);
        __half2* xh2 = reinterpret_cast<__half2*>(g_xh);
        #pragma unroll
        for (int i = 0; i < 8; ++i) {
            const size_t idx = base + i * 256;
            xh2[2 * idx]     = __floats2half2_rn(v[i].x, v[i].y);
            xh2[2 * idx + 1] = __floats2half2_rn(v[i].z, v[i].w);
        }
        return;
    }
    // ---- densify: indices sorted per row; duplicate runs summed in fp32 by
    // the run-leader thread — deterministic, no atomics.
    __shared__ __align__(16) float acc[IN_F];   // 16 KB
    __shared__ __align__(16) int   sm_[NNZ];    // 2 KB staged mask row
    __shared__ __align__(16) float sw_[NNZ];    // 2 KB staged weight row
    const int o = blockIdx.x - CONV_BLOCKS;
    const int tid = threadIdx.x;

    // stage mask/w rows (vectorized, .cs: read-once)
    if (tid < NNZ / 4) {
        reinterpret_cast<int4*>(sm_)[tid] =
            ldcs4i(reinterpret_cast<const int4*>(mask + (size_t)o * NNZ) + tid);
        reinterpret_cast<float4*>(sw_)[tid] =
            ldcs4(reinterpret_cast<const float4*>(w + (size_t)o * NNZ) + tid);
    }
    // zero-fill acc with float4 stores (4 rounds)
    {
        float4* a4 = reinterpret_cast<float4*>(acc);
        const float4 z = {0.f, 0.f, 0.f, 0.f};
        #pragma unroll
        for (int i = 0; i < IN_F / 4 / 256; ++i) a4[tid + i * 256] = z;
    }
    __syncthreads();

    #pragma unroll
    for (int jb = 0; jb < NNZ / 256; ++jb) {
        const int j = tid + jb * 256;
        const int m = sm_[j];
        if (j > 0 && sm_[j - 1] == m) continue;  // not the run leader
        float s = sw_[j];
        int jj = j + 1;
        while (jj < NNZ && sm_[jj] == m) { s += sw_[jj]; jj++; }
        acc[m] = s;  // unique owner, acc pre-zeroed
    }
    __syncthreads();

    // convert + store 4 halves (8B) per round, 4 rounds per thread
    {
        uint2* dst = reinterpret_cast<uint2*>(g_wh + (size_t)o * IN_F);
        #pragma unroll
        for (int i = 0; i < IN_F / 4 / 256; ++i) {
            const int q = tid + i * 256;            // 4-half group index
            uint2 pk;
            pk.x = h2_bits(__floats2half2_rn(acc[4 * q],     acc[4 * q + 1]));
            pk.y = h2_bits(__floats2half2_rn(acc[4 * q + 2], acc[4 * q + 3]));
            dst[q] = pk;
        }
    }
}

// ============================================================================
// Kernel 2: pipelined fp16 mma.sync GEMM.
//   out[T,O] = xh[T,In] * Wh[O,In]^T + bias
// CTA 128x128, BK=64, 3-stage mbarrier ring, 8 warps @ 64x32, 2 CTAs/SM.
// full[s]: cp.async async-path arrivals (count 256, noinc).
// empty[s]: count 8 — one arrive per warp (lane 0) after the warp's last
// LDSM of the stage (ldmatrix is warp-collective, in-order retired).
// Epilogue uses st.global.cs: the 64MB out stream is written once and never
// read, so evict-first stores keep g_xh/g_wh (64MB) resident in the 126MB
// L2 instead of being evicted by out's write-allocate (~48MB of operand
// DRAM re-reads measured in R15).
// ============================================================================
__global__ void __launch_bounds__(256, 2) k_gemm(const float* __restrict__ bias,
                                                 float* __restrict__ out) {
    extern __shared__ char smem[];
    const uint32_t sbase = smem_u32(smem);
    const int tid  = threadIdx.x;
    const int wid  = tid >> 5;
    const int lane = tid & 31;
    const int wm = (wid >> 2) * 64;   // warp row offset
    const int wn = (wid & 3) * 32;    // warp col offset
    const int tok0 = blockIdx.x * BM;
    const int o0   = blockIdx.y * BN;

    const uint32_t mb_full0  = sbase + MBAR_BASE;
    const uint32_t mb_empty0 = sbase + MBAR_BASE + 24;

    if (tid == 0) {
        #pragma unroll
        for (int s = 0; s < STAGES; ++s) {
            mbar_init(mb_full0 + s * 8, 256);   // cp.async arrivals (all threads)
            mbar_init(mb_empty0 + s * 8, 8);    // one arrive per warp
        }
    }
    __syncthreads();  // barriers visible before any use

    const __half* ga = g_xh + (size_t)tok0 * IN_F;
    const __half* gb = g_wh + (size_t)o0 * IN_F;

    const int ldrow = tid >> 3;        // 0..31
    const int ldc   = (tid & 7) * 16;  // byte offset within 128B row
    const size_t gkc = (size_t)(ldc >> 1);

    auto load_stage = [&](int it, int s) {
        const uint32_t sA = sbase + s * STAGE_BYTES;
        const uint32_t sB = sA + BM * BK * 2;
        const size_t gk = (size_t)it * BK + gkc;
        #pragma unroll
        for (int i = 0; i < 4; ++i) {
            const int row = ldrow + i * 32;
            const uint32_t off = SW128(row * 128 + ldc);
            cp_async16(sA + off, ga + (size_t)row * IN_F + gk);
            cp_async16(sB + off, gb + (size_t)row * IN_F + gk);
        }
        cp_async_mbar_arrive(mb_full0 + s * 8);
    };

    #pragma unroll
    for (int s = 0; s < STAGES; ++s) load_stage(s, s);

    float acc[4][4][4];
    #pragma unroll
    for (int i = 0; i < 4; ++i)
        #pragma unroll
        for (int j = 0; j < 4; ++j)
            #pragma unroll
            for (int k = 0; k < 4; ++k) acc[i][j][k] = 0.0f;

    const int a_m  = wm + (lane & 15);
    const int a_kb = (lane >> 4) * 16;
    const int b_n  = wn + (lane & 7) + ((lane >> 4) << 3);
    const int b_kb = ((lane >> 3) & 1) * 16;

    for (int j = 0; j < KITERS; ++j) {
        const int cs = j % 3;
        const uint32_t ph = (uint32_t)(j / 3) & 1;
        mbar_wait(mb_full0 + cs * 8, ph);

        const uint32_t sA = sbase + cs * STAGE_BYTES;
        const uint32_t sB = sA + BM * BK * 2;

        #pragma unroll
        for (int ks = 0; ks < BK / 16; ++ks) {
            const int kb = ks * 32;
            uint32_t af[4][4];
            #pragma unroll
            for (int tm = 0; tm < 4; ++tm)
                ldmatrix_x4(af[tm], sA + SW128((a_m + tm * 16) * 128 + kb + a_kb));
            uint32_t bf[2][4];
            #pragma unroll
            for (int tn2 = 0; tn2 < 2; ++tn2)
                ldmatrix_x4(bf[tn2], sB + SW128((b_n + tn2 * 16) * 128 + kb + b_kb));
            if (ks == BK / 16 - 1 && lane == 0)
                mbar_arrive(mb_empty0 + cs * 8);  // warp's stage reads all done
            #pragma unroll
            for (int tm = 0; tm < 4; ++tm)
                #pragma unroll
                for (int tn = 0; tn < 4; ++tn)
                    mma16816(acc[tm][tn], af[tm], bf[tn >> 1][(tn & 1) * 2],
                             bf[tn >> 1][(tn & 1) * 2 + 1]);
        }

        if (j + 3 < KITERS) {
            mbar_wait(mb_empty0 + cs * 8, ph);  // all 8 warps done reading cs
            load_stage(j + 3, cs);
        }
    }

    // ---- Epilogue: register -> gmem (streaming float2), + bias
    #pragma unroll
    for (int tm = 0; tm < 4; ++tm) {
        const int row = tok0 + wm + tm * 16 + (lane >> 2);
        #pragma unroll
        for (int tn = 0; tn < 4; ++tn) {
            const int col = o0 + wn + tn * 8 + 2 * (lane & 3);
            const float2 bv = *reinterpret_cast<const float2*>(bias + col);
            float2 v0 = {acc[tm][tn][0] + bv.x, acc[tm][tn][1] + bv.y};
            float2 v1 = {acc[tm][tn][2] + bv.x, acc[tm][tn][3] + bv.y};
            stcs2(out + (size_t)row * OUT_F + col, v0);
            stcs2(out + (size_t)(row + 8) * OUT_F + col, v1);
        }
    }
}

// ============================================================================
// Launch
// ============================================================================
extern "C" void kernel_launch(void* const* d_in, const int* in_sizes, int n_in,
                              void* d_out, int out_size) {
    const float* x    = (const float*)d_in[0];
    const float* w    = (const float*)d_in[1];
    const int*   mask = (const int*)d_in[2];
    const float* bias = (const float*)d_in[3];
    float* out = (float*)d_out;

    cudaFuncSetAttribute(k_gemm, cudaFuncAttributeMaxDynamicSharedMemorySize,
                         SMEM_TOTAL);

    k_prep<<<CONV_BLOCKS + OUT_F, 256>>>((const float4*)x, w, mask);
    k_gemm<<<dim3(T_TOKENS / BM, OUT_F / BN), 256, SMEM_TOTAL>>>(bias, out);
}